// round 1
// baseline (speedup 1.0000x reference)
#include <cuda_runtime.h>

// WarpingLayer: out = grid_sample(x, base_grid + flow, bilinear, zeros, align_corners=True) * validity_mask
// Shapes fixed by the dataset: x [8,128,128,256] f32, flow [8,2,128,256] f32, out [8,128,128,256] f32.
// height_im=128, width_im=256, div_flow=1  =>  ix = w + flow_x, iy = h + flow_y
// (computed below with the reference's exact fp32 op ordering to keep the
//  ones_val >= 0.99999 mask decision bit-consistent with the JAX reference).

namespace {

constexpr int B = 8;
constexpr int C = 128;
constexpr int H = 128;
constexpr int W = 256;
constexpr int HW = H * W;            // 32768
constexpr int THREADS = 256;

__global__ __launch_bounds__(THREADS) void warp_kernel(
    const float* __restrict__ x,
    const float* __restrict__ flow,
    float* __restrict__ out)
{
    const int idx = blockIdx.x * THREADS + threadIdx.x;   // over B*H*W = 262144
    const int w = idx & (W - 1);          // W = 256 -> low 8 bits
    const int h = (idx >> 8) & (H - 1);   // H = 128 -> next 7 bits
    const int b = idx >> 15;

    // flow[b, 0, h, w] and flow[b, 1, h, w]
    const int fbase = b * 2 * HW + h * W + w;
    const float fx = __ldg(flow + fbase);
    const float fy = __ldg(flow + fbase + HW);

    // Reproduce reference arithmetic order (no fma contraction):
    //   flo = (f * 2.0) / (dim-1) / 1
    //   g   = -1 + i * (2/(dim-1))          (linspace)
    //   coord = ((g + flo) + 1.0) * 0.5 * (dim-1)
    const float flo_w = __fmul_rn(__fdiv_rn(__fmul_rn(fx, 2.0f), (float)(W - 1)), 1.0f);
    const float flo_h = __fmul_rn(__fdiv_rn(__fmul_rn(fy, 2.0f), (float)(H - 1)), 1.0f);
    const float step_x = __fdiv_rn(2.0f, (float)(W - 1));
    const float step_y = __fdiv_rn(2.0f, (float)(H - 1));
    const float gx = __fadd_rn(-1.0f, __fmul_rn((float)w, step_x));
    const float gy = __fadd_rn(-1.0f, __fmul_rn((float)h, step_y));

    const float ix = __fmul_rn(__fmul_rn(__fadd_rn(__fadd_rn(gx, flo_w), 1.0f), 0.5f), (float)(W - 1));
    const float iy = __fmul_rn(__fmul_rn(__fadd_rn(__fadd_rn(gy, flo_h), 1.0f), 0.5f), (float)(H - 1));

    const float x0f = floorf(ix);
    const float y0f = floorf(iy);
    const float x1f = __fadd_rn(x0f, 1.0f);
    const float y1f = __fadd_rn(y0f, 1.0f);

    const float wx1 = __fadd_rn(ix, -x0f);
    const float wx0 = __fadd_rn(1.0f, -wx1);
    const float wy1 = __fadd_rn(iy, -y0f);
    const float wy0 = __fadd_rn(1.0f, -wy1);

    const bool vx0 = (x0f >= 0.0f) && (x0f <= (float)(W - 1));
    const bool vx1 = (x1f >= 0.0f) && (x1f <= (float)(W - 1));
    const bool vy0 = (y0f >= 0.0f) && (y0f <= (float)(H - 1));
    const bool vy1 = (y1f >= 0.0f) && (y1f <= (float)(H - 1));

    // Corner weights with validity folded in (reference: wv = w * valid)
    const float m00 = (vx0 && vy0) ? __fmul_rn(wx0, wy0) : 0.0f;
    const float m01 = (vx1 && vy0) ? __fmul_rn(wx1, wy0) : 0.0f;
    const float m10 = (vx0 && vy1) ? __fmul_rn(wx0, wy1) : 0.0f;
    const float m11 = (vx1 && vy1) ? __fmul_rn(wx1, wy1) : 0.0f;

    const float ones_val =
        __fadd_rn(__fadd_rn(__fadd_rn(m00, m01), m10), m11);

    float* po = out + (size_t)(b * C) * HW + h * W + w;

    if (ones_val < 0.99999f) {
        // Entire channel column is masked to zero — no gathers needed.
        #pragma unroll 8
        for (int c = 0; c < C; ++c) {
            *po = 0.0f;
            po += HW;
        }
        return;
    }

    // Clamped integer corner indices (reference clips then casts)
    const int xi0 = min(max((int)x0f, 0), W - 1);
    const int xi1 = min(max((int)x1f, 0), W - 1);
    const int yi0 = min(max((int)y0f, 0), H - 1);
    const int yi1 = min(max((int)y1f, 0), H - 1);

    const int o00 = yi0 * W + xi0;
    const int o01 = yi0 * W + xi1;
    const int o10 = yi1 * W + xi0;
    const int o11 = yi1 * W + xi1;

    const float* px = x + (size_t)(b * C) * HW;

    #pragma unroll 8
    for (int c = 0; c < C; ++c) {
        const float g00 = __ldg(px + o00);
        const float g01 = __ldg(px + o01);
        const float g10 = __ldg(px + o10);
        const float g11 = __ldg(px + o11);
        float v = g00 * m00;
        v = fmaf(g01, m01, v);
        v = fmaf(g10, m10, v);
        v = fmaf(g11, m11, v);
        *po = v;
        px += HW;
        po += HW;
    }
}

}  // namespace

extern "C" void kernel_launch(void* const* d_in, const int* in_sizes, int n_in,
                              void* d_out, int out_size) {
    const float* x    = (const float*)d_in[0];
    const float* flow = (const float*)d_in[1];
    float* out        = (float*)d_out;

    const int total = B * H * W;               // 262144 threads, one per pixel
    warp_kernel<<<total / THREADS, THREADS>>>(x, flow, out);
}

// round 2
// speedup vs baseline: 1.6751x; 1.6751x over previous
#include <cuda_runtime.h>

// WarpingLayer via channel-transpose:
//   Pass 1: x [B,C,H,W] -> x_t [B,H,W,C]   (coalesced tiled transpose)
//   Pass 2: per-pixel bilinear gather of 4 contiguous C-vectors from x_t,
//           smem-staged transpose back to [B,C,H,W] output.
// Mask arithmetic reproduces the JAX reference fp32 op ordering exactly.

namespace {

constexpr int B = 8;
constexpr int C = 128;
constexpr int H = 128;
constexpr int W = 256;
constexpr int HW = H * W;                   // 32768
constexpr long long TOT = (long long)B * C * HW;

// 134 MB scratch for the transposed image (allowed: __device__ global array).
__device__ float g_xt[(size_t)B * HW * C];

// ---------------- Pass 1: NCHW -> NHWC transpose ----------------
__global__ __launch_bounds__(256) void transpose_kernel(const float* __restrict__ x)
{
    __shared__ float tile[32][33];
    const int hw0 = blockIdx.x * 32;
    const int c0  = blockIdx.y * 32;
    const int b   = blockIdx.z;
    const int tx  = threadIdx.x;         // 0..31
    const int ty  = threadIdx.y;         // 0..7

    const float* px = x + (size_t)b * C * HW;
    #pragma unroll
    for (int i = 0; i < 4; ++i) {
        const int c = c0 + ty + i * 8;
        tile[ty + i * 8][tx] = px[(size_t)c * HW + hw0 + tx];
    }
    __syncthreads();
    float* pt = g_xt + (size_t)b * HW * C;
    #pragma unroll
    for (int i = 0; i < 4; ++i) {
        const int hw = hw0 + ty + i * 8;
        pt[(size_t)hw * C + c0 + tx] = tile[tx][ty + i * 8];
    }
}

// ---------------- Pass 2: gather + write-back ----------------
// Block = 256 threads = 8 warps; block covers 32 consecutive pixels (same b,h).
// Each warp computes 4 pixels; lane l handles channels 4l..4l+3 via LDG.128.
__global__ __launch_bounds__(256) void warp_gather_kernel(
    const float* __restrict__ flow,
    float* __restrict__ out)
{
    __shared__ float tile[32][129];      // [pixel][channel], pad -> conflict-free

    const int tid  = threadIdx.x;
    const int warp = tid >> 5;           // 0..7
    const int lane = tid & 31;

    const int pix_base = blockIdx.x * 32;            // aligned: same b,h for block
    const int b  = pix_base >> 15;
    const int h  = (pix_base >> 8) & (H - 1);
    const int w0 = pix_base & (W - 1);

    const float* xt = g_xt;

    #pragma unroll
    for (int pp = 0; pp < 4; ++pp) {
        const int p = warp * 4 + pp;                 // local pixel 0..31
        const int w = w0 + p;

        // flow[b,0,h,w], flow[b,1,h,w]  (same address all lanes -> broadcast)
        const int fbase = b * 2 * HW + h * W + w;
        const float fx = __ldg(flow + fbase);
        const float fy = __ldg(flow + fbase + HW);

        // Reference-exact fp32 ordering:
        const float flo_w = __fmul_rn(__fdiv_rn(__fmul_rn(fx, 2.0f), (float)(W - 1)), 1.0f);
        const float flo_h = __fmul_rn(__fdiv_rn(__fmul_rn(fy, 2.0f), (float)(H - 1)), 1.0f);
        const float step_x = __fdiv_rn(2.0f, (float)(W - 1));
        const float step_y = __fdiv_rn(2.0f, (float)(H - 1));
        const float gx = __fadd_rn(-1.0f, __fmul_rn((float)w, step_x));
        const float gy = __fadd_rn(-1.0f, __fmul_rn((float)h, step_y));

        const float ix = __fmul_rn(__fmul_rn(__fadd_rn(__fadd_rn(gx, flo_w), 1.0f), 0.5f), (float)(W - 1));
        const float iy = __fmul_rn(__fmul_rn(__fadd_rn(__fadd_rn(gy, flo_h), 1.0f), 0.5f), (float)(H - 1));

        const float x0f = floorf(ix);
        const float y0f = floorf(iy);
        const float x1f = __fadd_rn(x0f, 1.0f);
        const float y1f = __fadd_rn(y0f, 1.0f);

        const float wx1 = __fadd_rn(ix, -x0f);
        const float wx0 = __fadd_rn(1.0f, -wx1);
        const float wy1 = __fadd_rn(iy, -y0f);
        const float wy0 = __fadd_rn(1.0f, -wy1);

        const bool vx0 = (x0f >= 0.0f) && (x0f <= (float)(W - 1));
        const bool vx1 = (x1f >= 0.0f) && (x1f <= (float)(W - 1));
        const bool vy0 = (y0f >= 0.0f) && (y0f <= (float)(H - 1));
        const bool vy1 = (y1f >= 0.0f) && (y1f <= (float)(H - 1));

        const float m00 = (vx0 && vy0) ? __fmul_rn(wx0, wy0) : 0.0f;
        const float m01 = (vx1 && vy0) ? __fmul_rn(wx1, wy0) : 0.0f;
        const float m10 = (vx0 && vy1) ? __fmul_rn(wx0, wy1) : 0.0f;
        const float m11 = (vx1 && vy1) ? __fmul_rn(wx1, wy1) : 0.0f;

        const float ones_val = __fadd_rn(__fadd_rn(__fadd_rn(m00, m01), m10), m11);

        float v0, v1, v2, v3;
        if (ones_val < 0.99999f) {
            v0 = v1 = v2 = v3 = 0.0f;
        } else {
            const int xi0 = min(max((int)x0f, 0), W - 1);
            const int xi1 = min(max((int)x1f, 0), W - 1);
            const int yi0 = min(max((int)y0f, 0), H - 1);
            const int yi1 = min(max((int)y1f, 0), H - 1);

            const size_t row0 = (size_t)(b * HW + yi0 * W);
            const size_t row1 = (size_t)(b * HW + yi1 * W);
            const int cc = lane * 4;

            const float4 g00 = *(const float4*)(xt + (row0 + xi0) * C + cc);
            const float4 g01 = *(const float4*)(xt + (row0 + xi1) * C + cc);
            const float4 g10 = *(const float4*)(xt + (row1 + xi0) * C + cc);
            const float4 g11 = *(const float4*)(xt + (row1 + xi1) * C + cc);

            v0 = fmaf(g11.x, m11, fmaf(g10.x, m10, fmaf(g01.x, m01, g00.x * m00)));
            v1 = fmaf(g11.y, m11, fmaf(g10.y, m10, fmaf(g01.y, m01, g00.y * m00)));
            v2 = fmaf(g11.z, m11, fmaf(g10.z, m10, fmaf(g01.z, m01, g00.z * m00)));
            v3 = fmaf(g11.w, m11, fmaf(g10.w, m10, fmaf(g01.w, m01, g00.w * m00)));
        }

        // stage: smem[p][c]  (lanes write consecutive columns -> conflict-free)
        float* srow = &tile[p][lane * 4];
        srow[0] = v0; srow[1] = v1; srow[2] = v2; srow[3] = v3;
    }

    __syncthreads();

    // Write back in NCHW: warp = fixed channel, lanes = consecutive w (coalesced).
    const int p  = tid & 31;
    const int c0 = tid >> 5;                         // 0..7
    float* po = out + (size_t)b * C * HW + (size_t)h * W + w0 + p;
    #pragma unroll
    for (int i = 0; i < 16; ++i) {
        const int c = c0 + i * 8;
        po[(size_t)c * HW] = tile[p][c];             // stride-129 smem: conflict-free
    }
}

}  // namespace

extern "C" void kernel_launch(void* const* d_in, const int* in_sizes, int n_in,
                              void* d_out, int out_size) {
    const float* x    = (const float*)d_in[0];
    const float* flow = (const float*)d_in[1];
    float* out        = (float*)d_out;

    dim3 tgrid(HW / 32, C / 32, B);                  // (1024, 4, 8)
    dim3 tblock(32, 8);
    transpose_kernel<<<tgrid, tblock>>>(x);

    const int nblocks = (B * HW) / 32;               // 8192
    warp_gather_kernel<<<nblocks, 256>>>(flow, out);
}

// round 3
// speedup vs baseline: 1.8141x; 1.0829x over previous
#include <cuda_runtime.h>

// WarpingLayer via channel-transpose, v3:
//   Pass 1: x [B,C,H,W] -> x_t [B,H,W,C]  (float4-read tiled transpose, __ldcs on x)
//   Pass 2: REVERSED block order (reads x_t tail while L2-resident), per-pixel
//           bilinear gather of 4 contiguous C-vectors, smem-staged NCHW write
//           with __stcs (streaming stores protect x_t L2 residency).
// Mask arithmetic reproduces the JAX reference fp32 op ordering exactly.

namespace {

constexpr int B = 8;
constexpr int C = 128;
constexpr int H = 128;
constexpr int W = 256;
constexpr int HW = H * W;                   // 32768

// 134 MB scratch for the transposed image (allowed: __device__ global array).
__device__ float g_xt[(size_t)B * HW * C];

// ---------------- Pass 1: NCHW -> NHWC transpose ----------------
// Tile: 32 channels x 128 hw. Read: float4 along hw (coalesced 512B/warp).
// Write: scalar along C (coalesced 128B/warp). smem pad 133 -> (5*tx+hw)%32
// is a permutation => conflict-free column reads.
__global__ __launch_bounds__(256) void transpose_kernel(const float* __restrict__ x)
{
    __shared__ float tile[32][133];
    const int hw0 = blockIdx.x * 128;
    const int c0  = blockIdx.y * 32;
    const int b   = blockIdx.z;
    const int tx  = threadIdx.x & 31;
    const int ty  = threadIdx.x >> 5;        // 0..7

    const float* px = x + (size_t)b * C * HW;
    #pragma unroll
    for (int i = 0; i < 4; ++i) {
        const int cl = ty + i * 8;           // 0..31
        const float4 v = __ldcs((const float4*)(px + (size_t)(c0 + cl) * HW + hw0) + tx);
        float* t = &tile[cl][4 * tx];
        t[0] = v.x; t[1] = v.y; t[2] = v.z; t[3] = v.w;
    }
    __syncthreads();

    float* pt = g_xt + (size_t)b * HW * C;
    #pragma unroll
    for (int i = 0; i < 16; ++i) {
        const int hwl = ty + i * 8;          // 0..127
        pt[(size_t)(hw0 + hwl) * C + c0 + tx] = tile[tx][hwl];
    }
}

// ---------------- Pass 2: gather + write-back ----------------
// Block = 256 threads = 8 warps; block covers 32 consecutive pixels (same b,h).
// Each warp computes 4 pixels; lane l handles channels 4l..4l+3 via LDG.128.
// Blocks iterate in REVERSE pixel order to ride the L2-resident tail of x_t.
__global__ __launch_bounds__(256) void warp_gather_kernel(
    const float* __restrict__ flow,
    float* __restrict__ out)
{
    __shared__ float tile[32][129];      // [pixel][channel], pad -> conflict-free

    const int tid  = threadIdx.x;
    const int warp = tid >> 5;           // 0..7
    const int lane = tid & 31;

    const int pix_base = (gridDim.x - 1 - blockIdx.x) * 32;   // reversed order
    const int b  = pix_base >> 15;
    const int h  = (pix_base >> 8) & (H - 1);
    const int w0 = pix_base & (W - 1);

    const float* xt = g_xt;

    #pragma unroll
    for (int pp = 0; pp < 4; ++pp) {
        const int p = warp * 4 + pp;                 // local pixel 0..31
        const int w = w0 + p;

        // flow[b,0,h,w], flow[b,1,h,w]  (same address all lanes -> broadcast)
        const int fbase = b * 2 * HW + h * W + w;
        const float fx = __ldg(flow + fbase);
        const float fy = __ldg(flow + fbase + HW);

        // Reference-exact fp32 ordering:
        const float flo_w = __fmul_rn(__fdiv_rn(__fmul_rn(fx, 2.0f), (float)(W - 1)), 1.0f);
        const float flo_h = __fmul_rn(__fdiv_rn(__fmul_rn(fy, 2.0f), (float)(H - 1)), 1.0f);
        const float step_x = __fdiv_rn(2.0f, (float)(W - 1));
        const float step_y = __fdiv_rn(2.0f, (float)(H - 1));
        const float gx = __fadd_rn(-1.0f, __fmul_rn((float)w, step_x));
        const float gy = __fadd_rn(-1.0f, __fmul_rn((float)h, step_y));

        const float ix = __fmul_rn(__fmul_rn(__fadd_rn(__fadd_rn(gx, flo_w), 1.0f), 0.5f), (float)(W - 1));
        const float iy = __fmul_rn(__fmul_rn(__fadd_rn(__fadd_rn(gy, flo_h), 1.0f), 0.5f), (float)(H - 1));

        const float x0f = floorf(ix);
        const float y0f = floorf(iy);
        const float x1f = __fadd_rn(x0f, 1.0f);
        const float y1f = __fadd_rn(y0f, 1.0f);

        const float wx1 = __fadd_rn(ix, -x0f);
        const float wx0 = __fadd_rn(1.0f, -wx1);
        const float wy1 = __fadd_rn(iy, -y0f);
        const float wy0 = __fadd_rn(1.0f, -wy1);

        const bool vx0 = (x0f >= 0.0f) && (x0f <= (float)(W - 1));
        const bool vx1 = (x1f >= 0.0f) && (x1f <= (float)(W - 1));
        const bool vy0 = (y0f >= 0.0f) && (y0f <= (float)(H - 1));
        const bool vy1 = (y1f >= 0.0f) && (y1f <= (float)(H - 1));

        const float m00 = (vx0 && vy0) ? __fmul_rn(wx0, wy0) : 0.0f;
        const float m01 = (vx1 && vy0) ? __fmul_rn(wx1, wy0) : 0.0f;
        const float m10 = (vx0 && vy1) ? __fmul_rn(wx0, wy1) : 0.0f;
        const float m11 = (vx1 && vy1) ? __fmul_rn(wx1, wy1) : 0.0f;

        const float ones_val = __fadd_rn(__fadd_rn(__fadd_rn(m00, m01), m10), m11);

        float v0, v1, v2, v3;
        if (ones_val < 0.99999f) {
            v0 = v1 = v2 = v3 = 0.0f;
        } else {
            const int xi0 = min(max((int)x0f, 0), W - 1);
            const int xi1 = min(max((int)x1f, 0), W - 1);
            const int yi0 = min(max((int)y0f, 0), H - 1);
            const int yi1 = min(max((int)y1f, 0), H - 1);

            const size_t row0 = (size_t)(b * HW + yi0 * W);
            const size_t row1 = (size_t)(b * HW + yi1 * W);
            const int cc = lane * 4;

            const float4 g00 = *(const float4*)(xt + (row0 + xi0) * C + cc);
            const float4 g01 = *(const float4*)(xt + (row0 + xi1) * C + cc);
            const float4 g10 = *(const float4*)(xt + (row1 + xi0) * C + cc);
            const float4 g11 = *(const float4*)(xt + (row1 + xi1) * C + cc);

            v0 = fmaf(g11.x, m11, fmaf(g10.x, m10, fmaf(g01.x, m01, g00.x * m00)));
            v1 = fmaf(g11.y, m11, fmaf(g10.y, m10, fmaf(g01.y, m01, g00.y * m00)));
            v2 = fmaf(g11.z, m11, fmaf(g10.z, m10, fmaf(g01.z, m01, g00.z * m00)));
            v3 = fmaf(g11.w, m11, fmaf(g10.w, m10, fmaf(g01.w, m01, g00.w * m00)));
        }

        // stage: smem[p][c]  (lanes write consecutive columns -> conflict-free)
        float* srow = &tile[p][lane * 4];
        srow[0] = v0; srow[1] = v1; srow[2] = v2; srow[3] = v3;
    }

    __syncthreads();

    // Write back in NCHW: warp = fixed channel, lanes = consecutive w (coalesced).
    // Streaming stores: don't let output writes evict x_t from L2.
    const int p  = tid & 31;
    const int c0 = tid >> 5;                         // 0..7
    float* po = out + (size_t)b * C * HW + (size_t)h * W + w0 + p;
    #pragma unroll
    for (int i = 0; i < 16; ++i) {
        const int c = c0 + i * 8;
        __stcs(po + (size_t)c * HW, tile[p][c]);     // stride-129 smem: conflict-free
    }
}

}  // namespace

extern "C" void kernel_launch(void* const* d_in, const int* in_sizes, int n_in,
                              void* d_out, int out_size) {
    const float* x    = (const float*)d_in[0];
    const float* flow = (const float*)d_in[1];
    float* out        = (float*)d_out;

    dim3 tgrid(HW / 128, C / 32, B);                 // (256, 4, 8)
    transpose_kernel<<<tgrid, 256>>>(x);

    const int nblocks = (B * HW) / 32;               // 8192
    warp_gather_kernel<<<nblocks, 256>>>(flow, out);
}